// round 14
// baseline (speedup 1.0000x reference)
#include <cuda_runtime.h>
#include <cuda_bf16.h>
#include <cuda_fp16.h>
#include <math.h>

// Problem dims
#define T_STEPS 2048
#define BATCH   64
#define DIN     512
#define HDIM    512
#define G4      2048            // 4*H
#define M_ROWS  131072          // T*B
#define NBLK    128             // lstm CTAs
#define GNB     148             // gemm CTAs
#define NTILES  32768           // 1024 y-tiles(128 rows) x 32 x-tiles(64 cols)

typedef unsigned long long u64;
typedef unsigned int u32;

// Scratch (device globals: allocation-free contract)
// g_xproj layout: [t][cta(128)][batch(64)][q(4)][g(4)] fp32
__device__ float g_xproj[268435456];            // 1 GiB
__device__ __nv_bfloat16 g_xhi[67108864];       // X hi  (bf16)
__device__ __nv_bfloat16 g_xlo[67108864];       // X lo  (bf16)
__device__ __nv_bfloat16 g_wxthi[1048576];      // Wx^T hi [2048][512]
__device__ __nv_bfloat16 g_wxtlo[1048576];      // Wx^T lo
__device__ __half g_hf[2][32768];               // h state fp16 [buf][b*512+col]
__device__ unsigned long long g_arrive  = 0ULL;
__device__ unsigned long long g_release = 0ULL;
__device__ u32 g_ycnt[1024];                    // xproj y-tile progress (monotonic)

// ---------------------------------------------------------------------------
// PTX helpers
// ---------------------------------------------------------------------------
__device__ __forceinline__ u32 smem_u32(const void* p) {
    u32 a;
    asm("{ .reg .u64 t; cvta.to.shared.u64 t, %1; cvt.u32.u64 %0, t; }"
        : "=r"(a) : "l"(p));
    return a;
}
__device__ __forceinline__ void cpa16(u32 dst, const void* src) {
    asm volatile("cp.async.cg.shared.global [%0], [%1], 16;"
                 :: "r"(dst), "l"(src));
}
#define CP_COMMIT() asm volatile("cp.async.commit_group;" ::: "memory")

#define LDSM4(r0, r1, r2, r3, a) \
    asm volatile("ldmatrix.sync.aligned.m8n8.x4.shared.b16 {%0,%1,%2,%3}, [%4];" \
                 : "=r"(r0), "=r"(r1), "=r"(r2), "=r"(r3) : "r"(a))

#define MMA_BF16(c, a, b) \
    asm volatile("mma.sync.aligned.m16n8k16.row.col.f32.bf16.bf16.f32 " \
                 "{%0,%1,%2,%3}, {%4,%5,%6,%7}, {%8,%9}, {%0,%1,%2,%3};" \
                 : "+f"((c)[0]), "+f"((c)[1]), "+f"((c)[2]), "+f"((c)[3]) \
                 : "r"((a)[0]), "r"((a)[1]), "r"((a)[2]), "r"((a)[3]), \
                   "r"((b)[0]), "r"((b)[1]))

#define MMA_F16(c, a, b0r, b1r) \
    asm volatile("mma.sync.aligned.m16n8k16.row.col.f32.f16.f16.f32 " \
                 "{%0,%1,%2,%3}, {%4,%5,%6,%7}, {%8,%9}, {%0,%1,%2,%3};" \
                 : "+f"((c)[0]), "+f"((c)[1]), "+f"((c)[2]), "+f"((c)[3]) \
                 : "r"((a)[0]), "r"((a)[1]), "r"((a)[2]), "r"((a)[3]), \
                   "r"(b0r), "r"(b1r))

__device__ __forceinline__ void red_add_u32(u32* p, u32 v) {
    asm volatile("red.global.add.u32 [%0], %1;" :: "l"(p), "r"(v) : "memory");
}
__device__ __forceinline__ u32 ld_cg_u32(const u32* p) {
    u32 v;
    asm volatile("ld.global.cg.u32 %0, [%1];" : "=r"(v) : "l"(p) : "memory");
    return v;
}
__device__ __forceinline__ float4 ld_cg_f4(const float* p) {
    float4 v;
    asm volatile("ld.global.cg.v4.f32 {%0,%1,%2,%3}, [%4];"
                 : "=f"(v.x), "=f"(v.y), "=f"(v.z), "=f"(v.w)
                 : "l"(p) : "memory");
    return v;
}

// ---------------------------------------------------------------------------
// Conversion kernels: fp32 -> bf16 hi/lo split (for x_proj GEMM)
// ---------------------------------------------------------------------------
__global__ __launch_bounds__(256) void convert_x(const float* __restrict__ X) {
    size_t i = (size_t)blockIdx.x * 256 + threadIdx.x;
    float4 v = ((const float4*)X)[i];
    __nv_bfloat16 h0 = __float2bfloat16(v.x);
    __nv_bfloat16 h1 = __float2bfloat16(v.y);
    __nv_bfloat16 h2 = __float2bfloat16(v.z);
    __nv_bfloat16 h3 = __float2bfloat16(v.w);
    __nv_bfloat16 l0 = __float2bfloat16(v.x - __bfloat162float(h0));
    __nv_bfloat16 l1 = __float2bfloat16(v.y - __bfloat162float(h1));
    __nv_bfloat16 l2 = __float2bfloat16(v.z - __bfloat162float(h2));
    __nv_bfloat16 l3 = __float2bfloat16(v.w - __bfloat162float(h3));
    __nv_bfloat162* ph = (__nv_bfloat162*)g_xhi;
    __nv_bfloat162* pl = (__nv_bfloat162*)g_xlo;
    ph[i * 2]     = __nv_bfloat162(h0, h1);
    ph[i * 2 + 1] = __nv_bfloat162(h2, h3);
    pl[i * 2]     = __nv_bfloat162(l0, l1);
    pl[i * 2 + 1] = __nv_bfloat162(l2, l3);
}

__global__ __launch_bounds__(256) void convert_w(const float* __restrict__ Wx) {
    int idx = blockIdx.x * 256 + threadIdx.x;
    int k = idx >> 11, g = idx & 2047;
    float v = Wx[idx];
    __nv_bfloat16 h = __float2bfloat16(v);
    __nv_bfloat16 l = __float2bfloat16(v - __bfloat162float(h));
    g_wxthi[(size_t)g * 512 + k] = h;
    g_wxtlo[(size_t)g * 512 + k] = l;
}

// ---------------------------------------------------------------------------
// Fused persistent kernel:
//   blocks [0,128): LSTM recurrence; xproj consumed via L2 (ld.cg) only.
//   blocks [128,276): streaming xproj GEMM, tile 128(M)x64(N), 3-term bf16,
//     3-stage cp.async, tiles in increasing-t order, progress via g_ycnt.
// ---------------------------------------------------------------------------
#define APB 1040          // plane row pitch bytes (512 fp16 + 8 pad)
#define SM_A    0         // 64*1040 = 66560
#define SM_RED  66560     // 4096
#define SM_WST  70656     // W planes: hi 16*1040, lo 16*1040 (kept all run)
#define SM_TOTAL 103936

// GEMM smem layout (within the same 104KB dynamic block)
#define GA_B   10240      // A tile 128 rows * 80B
#define GB_B   5120       // B tile 64 rows * 80B
#define GSTAGE 15360

__device__ __forceinline__ void gemm_load_tile(
    u32 sA, u32 sB,
    const __nv_bfloat16* __restrict__ asrc,
    const __nv_bfloat16* __restrict__ bsrc,
    int kc, int tid)
{
#pragma unroll
    for (int p = 0; p < 2; p++) {
        int idx = tid + p * 256;
        int row = idx >> 2, seg = idx & 3;
        cpa16(sA + row * 80 + seg * 16,
              (const char*)(asrc + (size_t)row * 512 + kc) + seg * 16);
    }
    {
        int row = tid >> 2, seg = tid & 3;
        cpa16(sB + row * 80 + seg * 16,
              (const char*)(bsrc + (size_t)row * 512 + kc) + seg * 16);
    }
}

__global__ __launch_bounds__(256, 2) void fused_lstm(
    const float* __restrict__ Wh,   // [512][2048]
    const float* __restrict__ bh,   // [2048]
    const float* __restrict__ bx,   // [2048]
    float* __restrict__ out)        // [2][64][512]
{
    extern __shared__ char smem[];
    u32 sb = smem_u32(smem);
    const int tid  = threadIdx.x;
    const int lane = tid & 31;
    const int wid  = tid >> 5;

    if (blockIdx.x >= NBLK) {
        // =================== GEMM role ===================
        const int gid = blockIdx.x - NBLK;

#pragma unroll 1
        for (int tile = gid; tile < NTILES; tile += GNB) {
            const int ty = tile >> 5;        // y-tile: rows [ty*128, +128)
            const int tx = tile & 31;        // x-tile: cols [tx*64, +64)

            const __nv_bfloat16* a_hi = g_xhi + (size_t)ty * 128 * 512;
            const __nv_bfloat16* a_lo = g_xlo + (size_t)ty * 128 * 512;
            const __nv_bfloat16* b_hi = g_wxthi + (size_t)tx * 64 * 512;
            const __nv_bfloat16* b_lo = g_wxtlo + (size_t)tx * 64 * 512;

            float acc[8][4];
#pragma unroll
            for (int nt = 0; nt < 8; nt++)
#pragma unroll
                for (int r = 0; r < 4; r++) acc[nt][r] = 0.f;

            gemm_load_tile(sb,          sb + GA_B,          a_hi, b_hi, 0,  tid);
            CP_COMMIT();
            gemm_load_tile(sb + GSTAGE, sb + GSTAGE + GA_B, a_hi, b_hi, 32, tid);
            CP_COMMIT();

            int st = 0, pst = 2;
#pragma unroll 1
            for (int c = 0; c < 48; c++) {
                if (c < 47) {
                    asm volatile("cp.async.wait_group 1;" ::: "memory");
                } else {
                    asm volatile("cp.async.wait_group 0;" ::: "memory");
                }
                __syncthreads();

                if (c + 2 < 48) {
                    const int cn = c + 2;
                    const int s  = cn >> 4;
                    const int kc = (cn & 15) * 32;
                    const __nv_bfloat16* as = (s == 2) ? a_lo : a_hi;
                    const __nv_bfloat16* bs = (s == 1) ? b_lo : b_hi;
                    u32 base = sb + (u32)pst * GSTAGE;
                    gemm_load_tile(base, base + GA_B, as, bs, kc, tid);
                    CP_COMMIT();
                }

                const u32 sA = sb + (u32)st * GSTAGE;
                const u32 sB = sA + GA_B;

#pragma unroll
                for (int k16 = 0; k16 < 2; k16++) {
                    const int kb = k16 * 16;
                    u32 a_frag[4];
                    {
                        u32 addr = sA + (u32)((wid * 16 + (lane & 15)) * 40
                                              + kb + (lane >> 4) * 8) * 2;
                        LDSM4(a_frag[0], a_frag[1], a_frag[2], a_frag[3], addr);
                    }
                    u32 b_frag[8][2];
#pragma unroll
                    for (int ntp = 0; ntp < 4; ntp++) {
                        u32 addr = sB + (u32)((ntp * 16 + (lane & 15)) * 40
                                              + kb + (lane >> 4) * 8) * 2;
                        u32 r0, r1, r2, r3;
                        LDSM4(r0, r1, r2, r3, addr);
                        b_frag[2 * ntp][0]     = r0;
                        b_frag[2 * ntp][1]     = r2;
                        b_frag[2 * ntp + 1][0] = r1;
                        b_frag[2 * ntp + 1][1] = r3;
                    }
#pragma unroll
                    for (int nt = 0; nt < 8; nt++)
                        MMA_BF16(acc[nt], a_frag, b_frag[nt]);
                }

                st = (st == 2) ? 0 : st + 1;
                pst = (pst == 2) ? 0 : pst + 1;
            }

            // Epilogue: bias + permuted store
            const int mrow  = ty * 128 + wid * 16 + (lane >> 2);
            const int ncol0 = tx * 64 + (lane & 3) * 2;
#pragma unroll
            for (int nt = 0; nt < 8; nt++) {
                const int col = ncol0 + nt * 8;
                const float2 bs = __ldg((const float2*)(bx + col));
                const int g = col >> 9;
                const int hcol = col & 511;
                const size_t cb = (size_t)(hcol >> 2) * 1024 + (hcol & 3) * 4 + g;
                const int rA = mrow;
                const int rB = rA + 8;
                const size_t baseA = (size_t)(rA >> 6) * 131072 + (rA & 63) * 16;
                const size_t baseB = (size_t)(rB >> 6) * 131072 + (rB & 63) * 16;
                g_xproj[baseA + cb]     = acc[nt][0] + bs.x;
                g_xproj[baseA + cb + 4] = acc[nt][1] + bs.y;
                g_xproj[baseB + cb]     = acc[nt][2] + bs.x;
                g_xproj[baseB + cb + 4] = acc[nt][3] + bs.y;
            }
            __threadfence();
            __syncthreads();       // stores+fences done; also guards stage reuse
            if (tid == 0) red_add_u32(&g_ycnt[ty], 1);
        }
        return;
    }

    // =================== LSTM role ===================
    const int cta = blockIdx.x;
    const int c0  = cta * 4;
    const int grp = wid >> 2;     // k-half
    const int mw  = wid & 3;      // m-tile (16 batches)

    // Replay epoch from monotonic g_arrive (contamination < 128 per launch;
    // 262272 arrivals per full launch so the floor is exact).
    u64 a0;
    asm volatile("ld.volatile.global.u64 %0, [%1];" : "=l"(a0) : "l"(&g_arrive));
    const u32 ytarget = 32u * (u32)(a0 / (128ULL * 2049ULL)) + 32u;

    // --- Stage Wh slice into smem fp16 hi/lo (both planes stay resident)
    for (int idx = tid; idx < 16 * 512; idx += 256) {
        int n = idx & 15, k = idx >> 4;
        int q = n >> 2, g = n & 3;
        float v = Wh[(size_t)k * G4 + g * HDIM + c0 + q];
        __half h = __float2half_rn(v);
        __half l = __float2half_rn(v - __half2float(h));
        *(__half*)(smem + SM_WST + n * APB + k * 2)         = h;
        *(__half*)(smem + SM_WST + 16640 + n * APB + k * 2) = l;
    }
    __syncthreads();

    // --- W-hi fragments into registers; W-lo read from smem per step
    u32 bhi[16][4];
    const u32 wrow_h = sb + SM_WST + (u32)(lane & 15) * APB
                     + (u32)grp * 512 + (u32)(lane >> 4) * 16;
    const u32 wrow_l = wrow_h + 16640;
#pragma unroll
    for (int kk = 0; kk < 16; kk++) {
        LDSM4(bhi[kk][0], bhi[kk][1], bhi[kk][2], bhi[kk][3], wrow_h + kk * 32);
    }

    // --- Per-lane state identity: ONE state per thread.
    const int q    = ((lane >> 1) & 1) + 2 * (lane & 1);
    const int col  = c0 + q;
    const int bsel = mw * 16 + (lane >> 2) + grp * 8;

    float4 bhv;
    bhv.x = bh[0 * HDIM + col];
    bhv.y = bh[1 * HDIM + col];
    bhv.z = bh[2 * HDIM + col];
    bhv.w = bh[3 * HDIM + col];

    // Zero h buffer 0
    {
        int gt = cta * 256 + tid;
        if (gt < 16384) ((u32*)g_hf[0])[gt] = 0u;
    }

    // Initial grid barrier; tid0 additionally waits for xproj y-tile 0.
    __syncthreads();
    if (tid == 0) {
        __threadfence();
        unsigned long long tk = atomicAdd(&g_arrive, 1ULL) + 1ULL;
        unsigned long long n = (unsigned long long)NBLK;
        unsigned long long target = ((tk + n - 1ULL) / n) * n;
        if (tk == target) {
            atomicMax(&g_release, target);
        } else {
            unsigned long long r;
            do {
                asm volatile("ld.volatile.global.u64 %0, [%1];"
                             : "=l"(r) : "l"(&g_release));
            } while (r < target);
        }
        while (ld_cg_u32(&g_ycnt[0]) < ytarget) { __nanosleep(16); }
        __threadfence();
    }
    __syncthreads();

    float cst = 0.f, hsum = 0.f, csum = 0.f;

    const u32 arow = sb + SM_A + (u32)(mw * 16 + (lane & 15)) * APB
                   + (u32)grp * 512 + (u32)(lane >> 4) * 16;
    const int brow = mw * 16 + (lane >> 4);
    const u32 bseg = (u32)grp * 512 + (u32)(lane & 15) * 16;
    const u32 red_mine  = SM_RED + (u32)grp * 2048 + (u32)mw * 512 + (u32)lane * 16;
    const u32 red_other = SM_RED + (u32)(grp ^ 1) * 2048 + (u32)mw * 512 + (u32)lane * 16;

#pragma unroll 1
    for (int t = 0; t < T_STEPS; t++) {
        const int rb = t & 1;
        const __half* src = g_hf[rb];

        // x_proj for THIS step via L2 (ld.cg) — availability guaranteed by the
        // previous barrier's ycnt wait; bypasses L1 entirely.
        const float4 xc = ld_cg_f4(g_xproj + (size_t)t * 131072
                                   + (size_t)cta * 1024 + bsel * 16 + q * 4);

        // --- Warp-local h broadcast: 2 pipelined 4KB k-chunks
#pragma unroll
        for (int c2 = 0; c2 < 2; c2++) {
#pragma unroll
            for (int j = 0; j < 8; j++) {
                int row = brow + j * 2;
                u32 off = (u32)row * APB + (u32)c2 * 256 + bseg;
                size_t go = (size_t)row * 1024 + c2 * 256 + (bseg & 1023);
                cpa16(sb + SM_A + off, (const char*)src + go);
            }
            CP_COMMIT();
        }

        // --- MMA m16n16, pipelined across the two chunks
        float acc0[4] = {0.f, 0.f, 0.f, 0.f};
        float acc1[4] = {0.f, 0.f, 0.f, 0.f};

        asm volatile("cp.async.wait_group 1;" ::: "memory");
        __syncwarp(0xffffffffu);
#pragma unroll
        for (int kk = 0; kk < 8; kk++) {
            u32 a[4], bl[4];
            LDSM4(a[0], a[1], a[2], a[3], arow + kk * 32);
            LDSM4(bl[0], bl[1], bl[2], bl[3], wrow_l + kk * 32);
            MMA_F16(acc0, a, bhi[kk][0], bhi[kk][2]);
            MMA_F16(acc0, a, bl[0], bl[2]);
            MMA_F16(acc1, a, bhi[kk][1], bhi[kk][3]);
            MMA_F16(acc1, a, bl[1], bl[3]);
        }
        asm volatile("cp.async.wait_group 0;" ::: "memory");
        __syncwarp(0xffffffffu);
#pragma unroll
        for (int kk = 8; kk < 16; kk++) {
            u32 a[4], bl[4];
            LDSM4(a[0], a[1], a[2], a[3], arow + kk * 32);
            LDSM4(bl[0], bl[1], bl[2], bl[3], wrow_l + kk * 32);
            MMA_F16(acc0, a, bhi[kk][0], bhi[kk][2]);
            MMA_F16(acc0, a, bl[0], bl[2]);
            MMA_F16(acc1, a, bhi[kk][1], bhi[kk][3]);
            MMA_F16(acc1, a, bl[1], bl[3]);
        }

        // --- Cross-group split-K exchange
        {
            float4 ship;
            if (grp == 0) {
                ship.x = acc0[2]; ship.y = acc0[3];
                ship.z = acc1[2]; ship.w = acc1[3];
            } else {
                ship.x = acc0[0]; ship.y = acc0[1];
                ship.z = acc1[0]; ship.w = acc1[1];
            }
            *(float4*)(smem + red_mine) = ship;
        }
        __syncthreads();

        float v0, v1, v2, v3;
        {
            float4 r = *(const float4*)(smem + red_other);
            if (grp == 0) {
                v0 = acc0[0] + r.x; v1 = acc0[1] + r.y;
                v2 = acc1[0] + r.z; v3 = acc1[1] + r.w;
            } else {
                v0 = acc0[2] + r.x; v1 = acc0[3] + r.y;
                v2 = acc1[2] + r.z; v3 = acc1[3] + r.w;
            }
        }

        // --- Pair exchange: gather the 4 gates of (bsel, col)
        const bool odd = (lane & 1);
        const float s0 = odd ? v0 : v2;
        const float s1 = odd ? v1 : v3;
        const float r0 = __shfl_xor_sync(0xffffffffu, s0, 1);
        const float r1 = __shfl_xor_sync(0xffffffffu, s1, 1);

        float gi, gf, go, gz;
        if (!odd) { gi = v0; gf = v1; go = r0; gz = r1; }
        else      { gi = r0; gf = r1; go = v2; gz = v3; }

        gi += xc.x + bhv.x; gf += xc.y + bhv.y;
        go += xc.z + bhv.z; gz += xc.w + bhv.w;

        const float iv = 1.f / (1.f + __expf(-gi));
        const float fv = 1.f / (1.f + __expf(-gf));
        const float ov = 1.f / (1.f + __expf(-go));
        const float zv = 1.f - 2.f / (__expf(2.f * gz) + 1.f);
        cst = fmaf(iv, zv, fv * cst);
        const float hv = ov * (1.f - 2.f / (__expf(2.f * cst) + 1.f));

        hsum += hv; csum += cst;

        g_hf[rb ^ 1][bsel * HDIM + col] = __float2half_rn(hv);

        // --- Grid barrier; tid0 also waits for next step's xproj y-tile
        __syncthreads();
        if (tid == 0) {
            __threadfence();
            unsigned long long tk = atomicAdd(&g_arrive, 1ULL) + 1ULL;
            unsigned long long n = (unsigned long long)NBLK;
            unsigned long long target = ((tk + n - 1ULL) / n) * n;
            if (tk == target) {
                atomicMax(&g_release, target);
            } else {
                unsigned long long r;
                do {
                    asm volatile("ld.volatile.global.u64 %0, [%1];"
                                 : "=l"(r) : "l"(&g_release));
                } while (r < target);
            }
            if (t + 1 < T_STEPS) {
                const u32 yw = (u32)((t + 1) >> 1);
                while (ld_cg_u32(&g_ycnt[yw]) < ytarget) { __nanosleep(16); }
            }
            __threadfence();
        }
        __syncthreads();
    }

    const float inv = 1.0f / (float)T_STEPS;
    out[bsel * HDIM + col]                = hsum * inv;
    out[BATCH * HDIM + bsel * HDIM + col] = csum * inv;
}

// ---------------------------------------------------------------------------
extern "C" void kernel_launch(void* const* d_in, const int* in_sizes, int n_in,
                              void* d_out, int out_size) {
    const float* X  = (const float*)d_in[0];
    const float* Wx = (const float*)d_in[1];
    const float* bx = (const float*)d_in[2];
    const float* Wh = (const float*)d_in[3];
    const float* bh = (const float*)d_in[4];
    float* out = (float*)d_out;

    cudaFuncSetAttribute(fused_lstm,
                         cudaFuncAttributeMaxDynamicSharedMemorySize, SM_TOTAL);

    convert_x<<<65536, 256>>>(X);
    convert_w<<<4096, 256>>>(Wx);

    fused_lstm<<<NBLK + GNB, 256, SM_TOTAL>>>(Wh, bh, bx, out);
}

// round 15
// speedup vs baseline: 1.2284x; 1.2284x over previous
#include <cuda_runtime.h>
#include <cuda_fp16.h>
#include <math.h>

// Problem dims
#define T_STEPS 2048
#define BATCH   64
#define DIN     512
#define HDIM    512
#define G4      2048            // 4*H
#define M_ROWS  131072          // T*B
#define NBLK    128

typedef unsigned long long u64;
typedef unsigned int u32;

// Scratch (device globals: allocation-free contract)
// g_xproj layout: [t][cta(128)][batch(64)][q(4)][g(4)] fp32
__device__ float g_xproj[268435456];            // 1 GiB
__device__ __half g_xh[67108864];               // X fp16 (single plane)
__device__ __half g_wxt[1048576];               // Wx^T fp16 [2048][512]
__device__ __half g_hf[2][32768];               // h state fp16 [buf][b*512+col]
__device__ unsigned long long g_arrive  = 0ULL;
__device__ unsigned long long g_release = 0ULL;

// ---------------------------------------------------------------------------
// PTX helpers
// ---------------------------------------------------------------------------
__device__ __forceinline__ u32 smem_u32(const void* p) {
    u32 a;
    asm("{ .reg .u64 t; cvta.to.shared.u64 t, %1; cvt.u32.u64 %0, t; }"
        : "=r"(a) : "l"(p));
    return a;
}
__device__ __forceinline__ void cpa16(u32 dst, const void* src) {
    asm volatile("cp.async.cg.shared.global [%0], [%1], 16;"
                 :: "r"(dst), "l"(src));
}
#define CP_COMMIT() asm volatile("cp.async.commit_group;" ::: "memory")

#define LDSM4(r0, r1, r2, r3, a) \
    asm volatile("ldmatrix.sync.aligned.m8n8.x4.shared.b16 {%0,%1,%2,%3}, [%4];" \
                 : "=r"(r0), "=r"(r1), "=r"(r2), "=r"(r3) : "r"(a))

#define MMA_F16B(c, a, b) \
    asm volatile("mma.sync.aligned.m16n8k16.row.col.f32.f16.f16.f32 " \
                 "{%0,%1,%2,%3}, {%4,%5,%6,%7}, {%8,%9}, {%0,%1,%2,%3};" \
                 : "+f"((c)[0]), "+f"((c)[1]), "+f"((c)[2]), "+f"((c)[3]) \
                 : "r"((a)[0]), "r"((a)[1]), "r"((a)[2]), "r"((a)[3]), \
                   "r"((b)[0]), "r"((b)[1]))

#define MMA_F16(c, a, b0r, b1r) \
    asm volatile("mma.sync.aligned.m16n8k16.row.col.f32.f16.f16.f32 " \
                 "{%0,%1,%2,%3}, {%4,%5,%6,%7}, {%8,%9}, {%0,%1,%2,%3};" \
                 : "+f"((c)[0]), "+f"((c)[1]), "+f"((c)[2]), "+f"((c)[3]) \
                 : "r"((a)[0]), "r"((a)[1]), "r"((a)[2]), "r"((a)[3]), \
                   "r"(b0r), "r"(b1r))

// ---------------------------------------------------------------------------
// Conversion kernels: fp32 -> fp16 (single plane)
// ---------------------------------------------------------------------------
__global__ __launch_bounds__(256) void convert_x(const float* __restrict__ X) {
    size_t i = (size_t)blockIdx.x * 256 + threadIdx.x;   // 16777216 float4
    float4 v = ((const float4*)X)[i];
    __half2* ph = (__half2*)g_xh;
    ph[i * 2]     = __floats2half2_rn(v.x, v.y);
    ph[i * 2 + 1] = __floats2half2_rn(v.z, v.w);
}

__global__ __launch_bounds__(256) void convert_w(const float* __restrict__ Wx) {
    int idx = blockIdx.x * 256 + threadIdx.x;    // 1048576
    int k = idx >> 11, g = idx & 2047;
    g_wxt[(size_t)g * 512 + k] = __float2half_rn(Wx[idx]);
}

// ---------------------------------------------------------------------------
// Kernel 1: x_proj = X @ Wx + bx via mma.sync fp16 single-plane (K=512).
// 3-stage cp.async pipeline, one __syncthreads per 32-K chunk.
// Epilogue writes the PERMUTED layout [t][cta][batch][q][g].
// ---------------------------------------------------------------------------
#define TILE_B   10240          // 128 rows * 80 bytes
#define GSTAGE   20480          // A tile + B tile per stage
#define GSM_TOTAL (3 * GSTAGE)  // 61440

__device__ __forceinline__ void load_tile(
    u32 sA, u32 sB,
    const __half* __restrict__ asrc,
    const __half* __restrict__ bsrc,
    int kc, int tid)
{
#pragma unroll
    for (int p = 0; p < 2; p++) {
        int idx = tid + p * 256;
        int row = idx >> 2, seg = idx & 3;
        cpa16(sA + row * 80 + seg * 16,
              (const char*)(asrc + (size_t)row * 512 + kc) + seg * 16);
    }
#pragma unroll
    for (int p = 0; p < 2; p++) {
        int idx = tid + p * 256;
        int row = idx >> 2, seg = idx & 3;
        cpa16(sB + row * 80 + seg * 16,
              (const char*)(bsrc + (size_t)row * 512 + kc) + seg * 16);
    }
}

__global__ __launch_bounds__(256, 2) void gemm_xproj_hmma(
    const float* __restrict__ bias)
{
    extern __shared__ char gsm[];
    u32 sb = smem_u32(gsm);

    const int tid  = threadIdx.x;
    const int lane = tid & 31;
    const int wid  = tid >> 5;
    const int m0w  = (wid & 3) * 32;
    const int n0w  = (wid >> 2) * 64;

    const int bn = blockIdx.x * 128;
    const int m0 = blockIdx.y * 128;

    const __half* a_src = g_xh + (size_t)m0 * 512;
    const __half* b_src = g_wxt + (size_t)bn * 512;

    float acc[2][8][4];
#pragma unroll
    for (int mt = 0; mt < 2; mt++)
#pragma unroll
        for (int nt = 0; nt < 8; nt++)
#pragma unroll
            for (int r = 0; r < 4; r++) acc[mt][nt][r] = 0.f;

    // Prologue: chunks 0 and 1 into stages 0 and 1
    load_tile(sb,          sb + TILE_B,          a_src, b_src, 0,  tid);
    CP_COMMIT();
    load_tile(sb + GSTAGE, sb + GSTAGE + TILE_B, a_src, b_src, 32, tid);
    CP_COMMIT();

    int st = 0, pst = 2;
#pragma unroll 1
    for (int c = 0; c < 16; c++) {
        if (c < 15) {
            asm volatile("cp.async.wait_group 1;" ::: "memory");
        } else {
            asm volatile("cp.async.wait_group 0;" ::: "memory");
        }
        __syncthreads();

        if (c + 2 < 16) {
            const int kc = (c + 2) * 32;
            u32 base = sb + (u32)pst * GSTAGE;
            load_tile(base, base + TILE_B, a_src, b_src, kc, tid);
            CP_COMMIT();
        }

        const u32 sA = sb + (u32)st * GSTAGE;
        const u32 sB = sA + TILE_B;

#pragma unroll
        for (int k16 = 0; k16 < 2; k16++) {
            const int kb = k16 * 16;
            u32 a_frag[2][4];
#pragma unroll
            for (int mt = 0; mt < 2; mt++) {
                u32 addr = sA + (u32)((m0w + mt * 16 + (lane & 15)) * 40
                                      + kb + (lane >> 4) * 8) * 2;
                LDSM4(a_frag[mt][0], a_frag[mt][1], a_frag[mt][2], a_frag[mt][3], addr);
            }
            u32 b_frag[8][2];
#pragma unroll
            for (int ntp = 0; ntp < 4; ntp++) {
                u32 addr = sB + (u32)((n0w + ntp * 16 + (lane & 15)) * 40
                                      + kb + (lane >> 4) * 8) * 2;
                u32 r0, r1, r2, r3;
                LDSM4(r0, r1, r2, r3, addr);
                b_frag[2 * ntp][0]     = r0;
                b_frag[2 * ntp][1]     = r2;
                b_frag[2 * ntp + 1][0] = r1;
                b_frag[2 * ntp + 1][1] = r3;
            }
#pragma unroll
            for (int mt = 0; mt < 2; mt++)
#pragma unroll
                for (int nt = 0; nt < 8; nt++)
                    MMA_F16B(acc[mt][nt], a_frag[mt], b_frag[nt]);
        }

        st = (st == 2) ? 0 : st + 1;
        pst = (pst == 2) ? 0 : pst + 1;
    }

    const int mrow  = m0 + m0w + (lane >> 2);
    const int ncol0 = bn + n0w + (lane & 3) * 2;
#pragma unroll
    for (int mt = 0; mt < 2; mt++) {
#pragma unroll
        for (int nt = 0; nt < 8; nt++) {
            const int col = ncol0 + nt * 8;
            const float2 bs = __ldg((const float2*)(bias + col));
            const int g = col >> 9;
            const int hcol = col & 511;
            const size_t cb = (size_t)(hcol >> 2) * 1024 + (hcol & 3) * 4 + g;
            const int rA = mrow + mt * 16;
            const int rB = rA + 8;
            const size_t baseA = (size_t)(rA >> 6) * 131072 + (rA & 63) * 16;
            const size_t baseB = (size_t)(rB >> 6) * 131072 + (rB & 63) * 16;
            g_xproj[baseA + cb]     = acc[mt][nt][0] + bs.x;
            g_xproj[baseA + cb + 4] = acc[mt][nt][1] + bs.y;
            g_xproj[baseB + cb]     = acc[mt][nt][2] + bs.x;
            g_xproj[baseB + cb + 4] = acc[mt][nt][3] + bs.y;
        }
    }
}

// ---------------------------------------------------------------------------
// Kernel 2: persistent recurrence (R9/R12 structure). h fp16 single-plane;
// Wh fp16 SINGLE-plane in registers (lo plane dropped: 2 MMAs per k16).
// Centralized atomic barrier; warp-local pipelined broadcast.
// ---------------------------------------------------------------------------
#define APB 1040          // plane row pitch bytes (512 fp16 + 8 pad)
#define SM_A    0         // 64*1040 = 66560
#define SM_RED  66560     // 4096
#define SM_WST  70656     // W hi plane: 16*1040 = 16640
#define SM_TOTAL 87296

__device__ __forceinline__ void grid_barrier() {
    __syncthreads();
    if (threadIdx.x == 0) {
        __threadfence();
        unsigned long long t = atomicAdd(&g_arrive, 1ULL) + 1ULL;
        unsigned long long n = (unsigned long long)NBLK;
        unsigned long long target = ((t + n - 1ULL) / n) * n;
        if (t == target) {
            atomicMax(&g_release, target);
        } else {
            unsigned long long r;
            do {
                asm volatile("ld.volatile.global.u64 %0, [%1];"
                             : "=l"(r) : "l"(&g_release));
            } while (r < target);
        }
        __threadfence();
    }
    __syncthreads();
}

__global__ __launch_bounds__(256, 1) void lstm_seq(
    const float* __restrict__ Wh,   // [512][2048]
    const float* __restrict__ bh,   // [2048]
    float* __restrict__ out)        // [2][64][512]
{
    extern __shared__ char smem[];
    u32 sb = smem_u32(smem);

    const int tid  = threadIdx.x;
    const int cta  = blockIdx.x;
    const int c0   = cta * 4;
    const int lane = tid & 31;
    const int wid  = tid >> 5;
    const int grp  = wid >> 2;     // k-half: 0 -> k[0:256), 1 -> k[256:512)
    const int mw   = wid & 3;      // m-tile (16 batches)

    // --- Stage Wh slice into smem fp16 (single plane), rows n = q*4+g
    for (int idx = tid; idx < 16 * 512; idx += 256) {
        int n = idx & 15, k = idx >> 4;
        int q = n >> 2, g = n & 3;
        float v = Wh[(size_t)k * G4 + g * HDIM + c0 + q];
        *(__half*)(smem + SM_WST + n * APB + k * 2) = __float2half_rn(v);
    }
    __syncthreads();

    // --- B fragments into registers (held for the whole run)
    u32 bhi[16][4];
    {
        const u32 wrow_h = sb + SM_WST + (u32)(lane & 15) * APB
                         + (u32)grp * 512 + (u32)(lane >> 4) * 16;
#pragma unroll
        for (int kk = 0; kk < 16; kk++) {
            LDSM4(bhi[kk][0], bhi[kk][1], bhi[kk][2], bhi[kk][3], wrow_h + kk * 32);
        }
    }

    // --- Per-lane state identity: ONE state per thread.
    const int q    = ((lane >> 1) & 1) + 2 * (lane & 1);
    const int col  = c0 + q;
    const int bsel = mw * 16 + (lane >> 2) + grp * 8;

    float4 bhv;
    bhv.x = bh[0 * HDIM + col];
    bhv.y = bh[1 * HDIM + col];
    bhv.z = bh[2 * HDIM + col];
    bhv.w = bh[3 * HDIM + col];

    // Zero h buffer 0 (32768 halfs = 16384 u32)
    {
        int gt = cta * 256 + tid;
        if (gt < 16384) ((u32*)g_hf[0])[gt] = 0u;
    }

    // Preload x_proj for t = 0 (hidden under the initial barrier)
    float4 xc;
    {
        const float* xb = g_xproj + (size_t)cta * 1024 + bsel * 16 + q * 4;
        xc = *(const float4*)xb;
    }

    grid_barrier();

    float cst = 0.f, hsum = 0.f, csum = 0.f;

    const u32 arow = sb + SM_A + (u32)(mw * 16 + (lane & 15)) * APB
                   + (u32)grp * 512 + (u32)(lane >> 4) * 16;
    const int brow = mw * 16 + (lane >> 4);
    const u32 bseg = (u32)grp * 512 + (u32)(lane & 15) * 16;
    const u32 red_mine  = SM_RED + (u32)grp * 2048 + (u32)mw * 512 + (u32)lane * 16;
    const u32 red_other = SM_RED + (u32)(grp ^ 1) * 2048 + (u32)mw * 512 + (u32)lane * 16;

#pragma unroll 1
    for (int t = 0; t < T_STEPS; t++) {
        const int rb = t & 1;
        const __half* src = g_hf[rb];

        // --- Warp-local h broadcast: 2 pipelined 4KB k-chunks
#pragma unroll
        for (int c2 = 0; c2 < 2; c2++) {
#pragma unroll
            for (int j = 0; j < 8; j++) {
                int row = brow + j * 2;
                u32 off = (u32)row * APB + (u32)c2 * 256 + bseg;
                size_t go = (size_t)row * 1024 + c2 * 256 + (bseg & 1023);
                cpa16(sb + SM_A + off, (const char*)src + go);
            }
            CP_COMMIT();
        }

        // --- MMA m16n16, pipelined across the two chunks; B from registers
        float acc0[4] = {0.f, 0.f, 0.f, 0.f};
        float acc1[4] = {0.f, 0.f, 0.f, 0.f};

        asm volatile("cp.async.wait_group 1;" ::: "memory");
        __syncwarp(0xffffffffu);
#pragma unroll
        for (int kk = 0; kk < 8; kk++) {
            u32 a[4];
            LDSM4(a[0], a[1], a[2], a[3], arow + kk * 32);
            MMA_F16(acc0, a, bhi[kk][0], bhi[kk][2]);
            MMA_F16(acc1, a, bhi[kk][1], bhi[kk][3]);
        }
        asm volatile("cp.async.wait_group 0;" ::: "memory");
        __syncwarp(0xffffffffu);
#pragma unroll
        for (int kk = 8; kk < 16; kk++) {
            u32 a[4];
            LDSM4(a[0], a[1], a[2], a[3], arow + kk * 32);
            MMA_F16(acc0, a, bhi[kk][0], bhi[kk][2]);
            MMA_F16(acc1, a, bhi[kk][1], bhi[kk][3]);
        }

        // --- Cross-group split-K exchange
        {
            float4 ship;
            if (grp == 0) {
                ship.x = acc0[2]; ship.y = acc0[3];
                ship.z = acc1[2]; ship.w = acc1[3];
            } else {
                ship.x = acc0[0]; ship.y = acc0[1];
                ship.z = acc1[0]; ship.w = acc1[1];
            }
            *(float4*)(smem + red_mine) = ship;
        }
        __syncthreads();

        float v0, v1, v2, v3;
        {
            float4 r = *(const float4*)(smem + red_other);
            if (grp == 0) {
                v0 = acc0[0] + r.x; v1 = acc0[1] + r.y;
                v2 = acc1[0] + r.z; v3 = acc1[1] + r.w;
            } else {
                v0 = acc0[2] + r.x; v1 = acc0[3] + r.y;
                v2 = acc1[2] + r.z; v3 = acc1[3] + r.w;
            }
        }

        // --- Pair exchange within lane pairs: gather the 4 gates
        const bool odd = (lane & 1);
        const float s0 = odd ? v0 : v2;
        const float s1 = odd ? v1 : v3;
        const float r0 = __shfl_xor_sync(0xffffffffu, s0, 1);
        const float r1 = __shfl_xor_sync(0xffffffffu, s1, 1);

        float gi, gf, go, gz;
        if (!odd) { gi = v0; gf = v1; go = r0; gz = r1; }
        else      { gi = r0; gf = r1; go = v2; gz = v3; }

        gi += xc.x + bhv.x; gf += xc.y + bhv.y;
        go += xc.z + bhv.z; gz += xc.w + bhv.w;

        const float iv = 1.f / (1.f + __expf(-gi));
        const float fv = 1.f / (1.f + __expf(-gf));
        const float ov = 1.f / (1.f + __expf(-go));
        const float zv = 1.f - 2.f / (__expf(2.f * gz) + 1.f);
        cst = fmaf(iv, zv, fv * cst);
        const float hv = ov * (1.f - 2.f / (__expf(2.f * cst) + 1.f));

        hsum += hv; csum += cst;

        g_hf[rb ^ 1][bsel * HDIM + col] = __float2half_rn(hv);

        // Prefetch next step's x_proj (hides under barrier)
        if (t + 1 < T_STEPS) {
            const float* xb = g_xproj + (size_t)(t + 1) * 131072
                            + (size_t)cta * 1024 + bsel * 16 + q * 4;
            xc = *(const float4*)xb;
        }

        grid_barrier();
    }

    const float inv = 1.0f / (float)T_STEPS;
    out[bsel * HDIM + col]                = hsum * inv;
    out[BATCH * HDIM + bsel * HDIM + col] = csum * inv;
}

// ---------------------------------------------------------------------------
extern "C" void kernel_launch(void* const* d_in, const int* in_sizes, int n_in,
                              void* d_out, int out_size) {
    const float* X  = (const float*)d_in[0];
    const float* Wx = (const float*)d_in[1];
    const float* bx = (const float*)d_in[2];
    const float* Wh = (const float*)d_in[3];
    const float* bh = (const float*)d_in[4];
    float* out = (float*)d_out;

    cudaFuncSetAttribute(gemm_xproj_hmma,
                         cudaFuncAttributeMaxDynamicSharedMemorySize, GSM_TOTAL);
    cudaFuncSetAttribute(lstm_seq,
                         cudaFuncAttributeMaxDynamicSharedMemorySize, SM_TOTAL);

    convert_x<<<65536, 256>>>(X);
    convert_w<<<4096, 256>>>(Wx);

    dim3 gemm_grid(16, 1024);
    gemm_xproj_hmma<<<gemm_grid, 256, GSM_TOTAL>>>(bx);

    lstm_seq<<<NBLK, 256, SM_TOTAL>>>(Wh, bh, out);
}